// round 6
// baseline (speedup 1.0000x reference)
#include <cuda_runtime.h>
#include <cuda_bf16.h>
#include <mma.h>
#include <cstdint>

using namespace nvcuda;

#define VOCAB   50257
#define M_TOK   4096
#define K_HID   1024
#define N_PAD   50304          // 393 * 128
#define NT      393            // n tiles of 128
#define PARTW   400            // padded row width for g_part
#define NCLUST  3

// ---------------- scratch (__device__ globals; no cudaMalloc allowed) ----------------
__device__ __align__(128) __nv_bfloat16 g_xb[(size_t)M_TOK * K_HID];   // x bf16 [M][K]
__device__ __align__(128) __nv_bfloat16 g_lb[(size_t)K_HID * N_PAD];   // logits bf16 [K][N_PAD]
__device__ float g_part[(size_t)M_TOK * PARTW];                        // (token, n_tile) sum-exp partial
__device__ int   g_perm[M_TOK];                                        // sorted-pos -> orig token
__device__ int   g_tokcl[M_TOK];                                       // token -> cluster
__device__ int   g_yint[M_TOK];                                        // normalized int32 labels
__device__ int   g_cfirst[M_TOK / 128];
__device__ int   g_clast[M_TOK / 128];

// ---------------- k_prep_x: x f32 -> bf16 (scalar, alignment-safe) ----------------
__global__ void k_prep_x(const float* __restrict__ x) {
    int t = blockIdx.x * 256 + threadIdx.x;
    g_xb[t] = __float2bfloat16(x[t]);
}

// ---------------- k_prep_l: logits f32 [K][VOCAB] -> bf16 [K][N_PAD] ----------------
__global__ void k_prep_l(const float* __restrict__ logits) {
    int col = blockIdx.x * 128 + threadIdx.x;        // 0 .. 50303
    int k   = blockIdx.y;                            // 0 .. 1023
    float v = (col < VOCAB) ? logits[(size_t)k * VOCAB + col] : 0.0f;
    g_lb[(size_t)k * N_PAD + col] = __float2bfloat16(v);
}

// ---------------- k_sort: decode y (int32 vs int64 layout), group tokens by cluster ----------------
__global__ void k_sort(const int* __restrict__ y32) {
    __shared__ int cnt[NCLUST], cur[NCLUST];
    __shared__ int is64;
    int tid = threadIdx.x;

    // Layout detection: int64 little-endian labels < 2^31 => every odd 32-bit word is 0.
    if (tid == 0) {
        int odd_nonzero = 0;
        for (int i = 0; i < 64; i++) odd_nonzero |= y32[2 * i + 1];
        is64 = (odd_nonzero == 0) ? 1 : 0;
    }
    if (tid < NCLUST) cnt[tid] = 0;
    __syncthreads();

    for (int t = tid; t < M_TOK; t += 1024) {
        int yi = is64 ? y32[2 * t] : y32[t];         // low word of int64, or plain int32
        yi = max(0, min(VOCAB - 1, yi));             // clamp: never crash on bad decode
        g_yint[t] = yi;
        int c = yi < 20000 ? 0 : (yi < 40000 ? 1 : 2);
        g_tokcl[t] = c;
        atomicAdd(&cnt[c], 1);
    }
    __syncthreads();
    if (tid == 0) { cur[0] = 0; cur[1] = cnt[0]; cur[2] = cnt[0] + cnt[1]; }
    __syncthreads();
    for (int t = tid; t < M_TOK; t += 1024) {
        int pos = atomicAdd(&cur[g_tokcl[t]], 1);
        g_perm[pos] = t;
    }
    __syncthreads();
    if (tid < M_TOK / 128) {
        g_cfirst[tid] = g_tokcl[g_perm[tid * 128]];
        g_clast[tid]  = g_tokcl[g_perm[tid * 128 + 127]];
    }
}

// ---------------- k_gemm shared layout: single struct, 128B-aligned members ----------------
#define A_PITCH 24     // halves per A row (48 B)
#define B_PITCH 136    // halves per B row (272 B)
#define P_PITCH 40     // floats per patch row (160 B)
struct __align__(128) Smem {
    __align__(128) __nv_bfloat16 As[128 * A_PITCH];
    __align__(128) __nv_bfloat16 Bs[16 * B_PITCH];
    __align__(128) float patch[8][16 * P_PITCH];
    __align__(128) float ep[128][4];
    int rowperm[128];
    int rowcl[128];
};

// ---------------- k_gemm: WMMA bf16 GEMM + fused exp / per-tile row-sum partials ----------------
// CTA 128x128, 8 warps as 2(m) x 4(n); warp tile 64x32 = 4x2 wmma 16x16x16.
__global__ __launch_bounds__(256) void k_gemm() {
    const int m_tile = blockIdx.x, n_tile = blockIdx.y;
    const int TB[NCLUST] = {0, 156, 312};
    const int TE[NCLUST] = {157, 313, 393};
    {
        int cf = g_cfirst[m_tile], cl = g_clast[m_tile];
        if (n_tile < TB[cf] || n_tile >= TE[cl]) return;   // outside this m-tile's cluster span
    }

    __shared__ Smem s;

    const int tid = threadIdx.x, lane = tid & 31, wid = tid >> 5;
    const int wm = wid >> 2, wn = wid & 3;

    if (tid < 128) {
        int o = g_perm[m_tile * 128 + tid];
        s.rowperm[tid] = o;
        s.rowcl[tid] = g_tokcl[o];
    }
    __syncthreads();

    wmma::fragment<wmma::accumulator, 16, 16, 16, float> acc[4][2];
#pragma unroll
    for (int fm = 0; fm < 4; fm++)
#pragma unroll
        for (int fn = 0; fn < 2; fn++) wmma::fill_fragment(acc[fm][fn], 0.0f);

    const int ar = tid >> 1, ah = (tid & 1) * 8;     // A staging: 2 threads/row
    const int bk = tid >> 4, bc = (tid & 15) * 8;    // B staging: 16 threads/k-row
    const size_t abase = (size_t)s.rowperm[ar] * K_HID + ah;
    const size_t bbase = (size_t)bk * N_PAD + (size_t)n_tile * 128 + bc;

    for (int k0 = 0; k0 < K_HID; k0 += 16) {
        *(uint4*)&s.As[ar * A_PITCH + ah] = *(const uint4*)(g_xb + abase + k0);
        *(uint4*)&s.Bs[bk * B_PITCH + bc] = *(const uint4*)(g_lb + bbase + (size_t)k0 * N_PAD);
        __syncthreads();

        wmma::fragment<wmma::matrix_b, 16, 16, 16, __nv_bfloat16, wmma::row_major> bf[2];
#pragma unroll
        for (int fn = 0; fn < 2; fn++)
            wmma::load_matrix_sync(bf[fn], &s.Bs[wn * 32 + fn * 16], B_PITCH);
#pragma unroll
        for (int fm = 0; fm < 4; fm++) {
            wmma::fragment<wmma::matrix_a, 16, 16, 16, __nv_bfloat16, wmma::row_major> af;
            wmma::load_matrix_sync(af, &s.As[(wm * 64 + fm * 16) * A_PITCH], A_PITCH);
            wmma::mma_sync(acc[fm][0], af, bf[0], acc[fm][0]);
            wmma::mma_sync(acc[fm][1], af, bf[1], acc[fm][1]);
        }
        __syncthreads();
    }

    // Epilogue: exp + cluster-masked row sums, deterministic fixed-order reduction.
    const int r16 = lane & 15, ch = lane >> 4;
    const int vbase = n_tile * 128 + wn * 32 + ch * 16;
#pragma unroll
    for (int fm = 0; fm < 4; fm++) {
        wmma::store_matrix_sync(&s.patch[wid][0],  acc[fm][0], P_PITCH, wmma::mem_row_major);
        wmma::store_matrix_sync(&s.patch[wid][16], acc[fm][1], P_PITCH, wmma::mem_row_major);
        __syncwarp();
        int rloc = wm * 64 + fm * 16 + r16;
        int crow = s.rowcl[rloc];
        float sum = 0.0f;
#pragma unroll
        for (int j = 0; j < 16; j++) {
            int vc = vbase + j;
            int ccol = vc < 20000 ? 0 : (vc < 40000 ? 1 : (vc < VOCAB ? 2 : 3));
            float v = s.patch[wid][r16 * P_PITCH + ch * 16 + j];
            if (ccol == crow) sum += __expf(v);
        }
        sum += __shfl_xor_sync(0xffffffffu, sum, 16);
        if (lane < 16) s.ep[rloc][wn] = sum;
        __syncwarp();
    }
    __syncthreads();
    if (tid < 128) {
        float tot = s.ep[tid][0] + s.ep[tid][1] + s.ep[tid][2] + s.ep[tid][3];  // fixed order
        g_part[(size_t)s.rowperm[tid] * PARTW + n_tile] = tot;
    }
}

// ---------------- k_final: per-token NLL (fp32), one warp per token ----------------
__global__ void k_final(const float* __restrict__ x,
                        const float* __restrict__ Wc, const float* __restrict__ logits,
                        float* __restrict__ out) {
    const int TB[NCLUST] = {0, 156, 312};
    const int TE[NCLUST] = {157, 313, 393};
    int warp = threadIdx.x >> 5, lane = threadIdx.x & 31;
    int token = blockIdx.x * 8 + warp;
    const float* xr = x + (size_t)token * K_HID;

    float xv[32];
#pragma unroll
    for (int i = 0; i < 32; i++) xv[i] = xr[i * 32 + lane];

    float s0 = 0.f, s1 = 0.f, s2 = 0.f;
#pragma unroll
    for (int i = 0; i < 32; i++) {
        int h = i * 32 + lane;
        s0 = fmaf(xv[i], Wc[h], s0);
        s1 = fmaf(xv[i], Wc[K_HID + h], s1);
        s2 = fmaf(xv[i], Wc[2 * K_HID + h], s2);
    }

    int yi = g_yint[token];
    int c = g_tokcl[token];
    float tg = 0.f;
#pragma unroll
    for (int i = 0; i < 32; i++) {
        int h = i * 32 + lane;
        tg = fmaf(xv[i], logits[(size_t)h * VOCAB + yi], tg);
    }

    float se = 0.f;                                   // fixed lane->tile mapping: deterministic
    for (int t = TB[c] + lane; t < TE[c]; t += 32)
        se += g_part[(size_t)token * PARTW + t];

#pragma unroll
    for (int o = 16; o; o >>= 1) {
        s0 += __shfl_xor_sync(0xffffffffu, s0, o);
        s1 += __shfl_xor_sync(0xffffffffu, s1, o);
        s2 += __shfl_xor_sync(0xffffffffu, s2, o);
        tg += __shfl_xor_sync(0xffffffffu, tg, o);
        se += __shfl_xor_sync(0xffffffffu, se, o);
    }

    if (lane == 0) {
        float m = fmaxf(s0, fmaxf(s1, s2));
        float lse3 = m + logf(expf(s0 - m) + expf(s1 - m) + expf(s2 - m));
        float sc = (c == 0) ? s0 : ((c == 1) ? s1 : s2);
        float cll = sc - lse3;                        // cluster log-prob
        float tlp = tg - logf(se);                    // tail target log-prob
        out[token] = -cll - tlp;
    }
}

// ---------------- launch ----------------
extern "C" void kernel_launch(void* const* d_in, const int* in_sizes, int n_in,
                              void* d_out, int out_size) {
    const float* x      = (const float*)d_in[0];
    const int*   y32    = (const int*)d_in[1];       // int32 OR int64 words; decoded in k_sort
    const float* Wc     = (const float*)d_in[2];
    const float* logits = (const float*)d_in[3];
    float*       out    = (float*)d_out;

    k_prep_x<<<M_TOK * K_HID / 256, 256>>>(x);
    k_prep_l<<<dim3(N_PAD / 128, K_HID), 128>>>(logits);
    k_sort<<<1, 1024>>>(y32);
    k_gemm<<<dim3(M_TOK / 128, NT), 256>>>();
    k_final<<<M_TOK / 8, 256>>>(x, Wc, logits, out);
}

// round 8
// speedup vs baseline: 1.3673x; 1.3673x over previous
#include <cuda_runtime.h>
#include <cuda_bf16.h>
#include <mma.h>
#include <cstdint>

using namespace nvcuda;

#define VOCAB   50257
#define M_TOK   4096
#define K_HID   1024
#define N_PAD   50304          // 393 * 128
#define NT      393
#define PARTW   400
#define NCLUST  3
#define NCHUNK  32             // K chunks of 32

// ---------------- scratch ----------------
__device__ __align__(128) __nv_bfloat16 g_xb[(size_t)M_TOK * K_HID];   // x bf16 [M][K]
__device__ __align__(128) __nv_bfloat16 g_lb[(size_t)K_HID * N_PAD];   // logits bf16 [K][N_PAD]
__device__ float g_part[(size_t)M_TOK * PARTW];
__device__ int   g_perm[M_TOK];
__device__ int   g_tokcl[M_TOK];
__device__ int   g_yint[M_TOK];
__device__ int   g_cfirst[M_TOK / 128];
__device__ int   g_clast[M_TOK / 128];

// ---------------- k_prep_x: x f32 -> bf16 (scalar, proven safe) ----------------
__global__ void k_prep_x(const float* __restrict__ x) {
    int t = blockIdx.x * 256 + threadIdx.x;
    g_xb[t] = __float2bfloat16(x[t]);
}

// ---------------- k_prep_l: logits f32 [K][VOCAB] -> bf16 [K][N_PAD] ----------------
__global__ void k_prep_l(const float* __restrict__ logits) {
    int col = blockIdx.x * 128 + threadIdx.x;
    int k   = blockIdx.y;
    float v = (col < VOCAB) ? logits[(size_t)k * VOCAB + col] : 0.0f;
    g_lb[(size_t)k * N_PAD + col] = __float2bfloat16(v);
}

// ---------------- k_sort: decode y (int32/int64), group tokens by cluster ----------------
__global__ void k_sort(const int* __restrict__ y32) {
    __shared__ int cnt[NCLUST], cur[NCLUST];
    __shared__ int is64;
    int tid = threadIdx.x;
    if (tid == 0) {
        int odd = 0;
        for (int i = 0; i < 64; i++) odd |= y32[2 * i + 1];
        is64 = (odd == 0) ? 1 : 0;
    }
    if (tid < NCLUST) cnt[tid] = 0;
    __syncthreads();
    for (int t = tid; t < M_TOK; t += 1024) {
        int yi = is64 ? y32[2 * t] : y32[t];
        yi = max(0, min(VOCAB - 1, yi));
        g_yint[t] = yi;
        int c = yi < 20000 ? 0 : (yi < 40000 ? 1 : 2);
        g_tokcl[t] = c;
        atomicAdd(&cnt[c], 1);
    }
    __syncthreads();
    if (tid == 0) { cur[0] = 0; cur[1] = cnt[0]; cur[2] = cnt[0] + cnt[1]; }
    __syncthreads();
    for (int t = tid; t < M_TOK; t += 1024) {
        int pos = atomicAdd(&cur[g_tokcl[t]], 1);
        g_perm[pos] = t;
    }
    __syncthreads();
    if (tid < M_TOK / 128) {
        g_cfirst[tid] = g_tokcl[g_perm[tid * 128]];
        g_clast[tid]  = g_tokcl[g_perm[tid * 128 + 127]];
    }
}

// ---------------- k_gemm smem: double-buffered stages, union'd with epilogue ----------------
#define A_PITCH 40     // halves per A row (80 B)
#define B_PITCH 136    // halves per B k-row (272 B)
#define P_PITCH 40     // floats per patch row
struct MLStage {
    __align__(16) __nv_bfloat16 A[128 * A_PITCH];   // 10240 B  [m][k] chunk K=32
    __align__(16) __nv_bfloat16 B[32 * B_PITCH];    //  8704 B  [k][n]
};
struct __align__(128) SmemU {
    union {
        MLStage st[2];                              // 37888 B mainloop
        struct {                                    // 22528 B epilogue
            float patch[8][16 * P_PITCH];
            float ep[128][4];
        } e;
    } u;
    int rowperm[128];
    int rowcl[128];
};

__device__ __forceinline__ void cp16(void* dst, const void* src) {
    uint32_t d = (uint32_t)__cvta_generic_to_shared(dst);
    asm volatile("cp.async.cg.shared.global [%0], [%1], 16;" :: "r"(d), "l"(src));
}

// ---------------- k_gemm: WMMA bf16, cp.async double-buffered ----------------
// CTA 128x128, 8 warps 2(m) x 4(n), warp tile 64x32 = 4x2 wmma 16x16x16.
__global__ __launch_bounds__(256) void k_gemm() {
    const int m_tile = blockIdx.x, n_tile = blockIdx.y;
    const int TB[NCLUST] = {0, 156, 312};
    const int TE[NCLUST] = {157, 313, 393};
    {
        int cf = g_cfirst[m_tile], cl = g_clast[m_tile];
        if (n_tile < TB[cf] || n_tile >= TE[cl]) return;
    }

    __shared__ SmemU s;
    const int tid = threadIdx.x, lane = tid & 31, wid = tid >> 5;
    const int wm = wid >> 2, wn = wid & 3;

    if (tid < 128) {
        int o = g_perm[m_tile * 128 + tid];
        s.rowperm[tid] = o;
        s.rowcl[tid] = g_tokcl[o];
    }
    __syncthreads();

    wmma::fragment<wmma::accumulator, 16, 16, 16, float> acc[4][2];
#pragma unroll
    for (int fm = 0; fm < 4; fm++)
#pragma unroll
        for (int fn = 0; fn < 2; fn++) wmma::fill_fragment(acc[fm][fn], 0.0f);

    // per-thread staging tasks (2 x 16B for A, 2 x 16B for B per stage)
    const int a0r = tid >> 1, a0s = tid & 1;             // task i=0: rows 0..127? (see below)
    (void)a0r; (void)a0s;

    // issue stage c into buffer buf
    auto issue = [&](int c, int buf) {
#pragma unroll
        for (int i = 0; i < 2; i++) {
            int t = tid + i * 256;                       // 0..511
            int ar = t >> 2, as = t & 3;                 // A: 128 rows x 4 segs
            cp16(&s.u.st[buf].A[ar * A_PITCH + as * 8],
                 g_xb + (size_t)s.rowperm[ar] * K_HID + c * 32 + as * 8);
            int br = t >> 4, bs = t & 15;                // B: 32 k-rows x 16 segs
            cp16(&s.u.st[buf].B[br * B_PITCH + bs * 8],
                 g_lb + (size_t)(c * 32 + br) * N_PAD + (size_t)n_tile * 128 + bs * 8);
        }
        asm volatile("cp.async.commit_group;" ::: "memory");
    };

    issue(0, 0);
    for (int c = 0; c < NCHUNK; c++) {
        if (c + 1 < NCHUNK) {
            issue(c + 1, (c + 1) & 1);
            asm volatile("cp.async.wait_group 1;" ::: "memory");
        } else {
            asm volatile("cp.async.wait_group 0;" ::: "memory");
        }
        __syncthreads();

        const MLStage& st = s.u.st[c & 1];
#pragma unroll
        for (int ks = 0; ks < 2; ks++) {
            const int kk = ks * 16;
            wmma::fragment<wmma::matrix_b, 16, 16, 16, __nv_bfloat16, wmma::row_major> bf[2];
#pragma unroll
            for (int fn = 0; fn < 2; fn++)
                wmma::load_matrix_sync(bf[fn], &st.B[kk * B_PITCH + wn * 32 + fn * 16], B_PITCH);
#pragma unroll
            for (int fm = 0; fm < 4; fm++) {
                wmma::fragment<wmma::matrix_a, 16, 16, 16, __nv_bfloat16, wmma::row_major> af;
                wmma::load_matrix_sync(af, &st.A[(wm * 64 + fm * 16) * A_PITCH + kk], A_PITCH);
                wmma::mma_sync(acc[fm][0], af, bf[0], acc[fm][0]);
                wmma::mma_sync(acc[fm][1], af, bf[1], acc[fm][1]);
            }
        }
        __syncthreads();
    }

    // Epilogue (reuses mainloop smem): exp + cluster-masked row sums, fixed order.
    const int r16 = lane & 15, ch = lane >> 4;
    const int vbase = n_tile * 128 + wn * 32 + ch * 16;
#pragma unroll
    for (int fm = 0; fm < 4; fm++) {
        wmma::store_matrix_sync(&s.u.e.patch[wid][0],  acc[fm][0], P_PITCH, wmma::mem_row_major);
        wmma::store_matrix_sync(&s.u.e.patch[wid][16], acc[fm][1], P_PITCH, wmma::mem_row_major);
        __syncwarp();
        int rloc = wm * 64 + fm * 16 + r16;
        int crow = s.rowcl[rloc];
        float sum = 0.0f;
#pragma unroll
        for (int j = 0; j < 16; j++) {
            int vc = vbase + j;
            int ccol = vc < 20000 ? 0 : (vc < 40000 ? 1 : (vc < VOCAB ? 2 : 3));
            float v = s.u.e.patch[wid][r16 * P_PITCH + ch * 16 + j];
            if (ccol == crow) sum += __expf(v);
        }
        sum += __shfl_xor_sync(0xffffffffu, sum, 16);
        if (lane < 16) s.u.e.ep[rloc][wn] = sum;
        __syncwarp();
    }
    __syncthreads();
    if (tid < 128) {
        float tot = s.u.e.ep[tid][0] + s.u.e.ep[tid][1] + s.u.e.ep[tid][2] + s.u.e.ep[tid][3];
        g_part[(size_t)s.rowperm[tid] * PARTW + n_tile] = tot;
    }
}

// ---------------- k_final: per-token NLL (fp32), one warp per token ----------------
__global__ void k_final(const float* __restrict__ x,
                        const float* __restrict__ Wc, const float* __restrict__ logits,
                        float* __restrict__ out) {
    const int TB[NCLUST] = {0, 156, 312};
    const int TE[NCLUST] = {157, 313, 393};
    int warp = threadIdx.x >> 5, lane = threadIdx.x & 31;
    int token = blockIdx.x * 8 + warp;
    const float* xr = x + (size_t)token * K_HID;

    float xv[32];
#pragma unroll
    for (int i = 0; i < 32; i++) xv[i] = xr[i * 32 + lane];

    float s0 = 0.f, s1 = 0.f, s2 = 0.f;
#pragma unroll
    for (int i = 0; i < 32; i++) {
        int h = i * 32 + lane;
        s0 = fmaf(xv[i], Wc[h], s0);
        s1 = fmaf(xv[i], Wc[K_HID + h], s1);
        s2 = fmaf(xv[i], Wc[2 * K_HID + h], s2);
    }

    int yi = g_yint[token];
    int c  = g_tokcl[token];
    float tg = 0.f;
#pragma unroll
    for (int i = 0; i < 32; i++) {
        int h = i * 32 + lane;
        tg = fmaf(xv[i], logits[(size_t)h * VOCAB + yi], tg);
    }

    float se = 0.f;
    for (int t = TB[c] + lane; t < TE[c]; t += 32)
        se += g_part[(size_t)token * PARTW + t];

#pragma unroll
    for (int o = 16; o; o >>= 1) {
        s0 += __shfl_xor_sync(0xffffffffu, s0, o);
        s1 += __shfl_xor_sync(0xffffffffu, s1, o);
        s2 += __shfl_xor_sync(0xffffffffu, s2, o);
        tg += __shfl_xor_sync(0xffffffffu, tg, o);
        se += __shfl_xor_sync(0xffffffffu, se, o);
    }

    if (lane == 0) {
        float m = fmaxf(s0, fmaxf(s1, s2));
        float lse3 = m + logf(expf(s0 - m) + expf(s1 - m) + expf(s2 - m));
        float sc = (c == 0) ? s0 : ((c == 1) ? s1 : s2);
        out[token] = -(sc - lse3) - (tg - logf(se));
    }
}

// ---------------- launch ----------------
extern "C" void kernel_launch(void* const* d_in, const int* in_sizes, int n_in,
                              void* d_out, int out_size) {
    const float* x      = (const float*)d_in[0];
    const int*   y32    = (const int*)d_in[1];
    const float* Wc     = (const float*)d_in[2];
    const float* logits = (const float*)d_in[3];
    float*       out    = (float*)d_out;

    k_prep_x<<<M_TOK * K_HID / 256, 256>>>(x);
    k_prep_l<<<dim3(N_PAD / 128, K_HID), 128>>>(logits);
    k_sort<<<1, 1024>>>(y32);
    k_gemm<<<dim3(M_TOK / 128, NT), 256>>>();     // m fastest -> B stripe L2-resident
    k_final<<<M_TOK / 8, 256>>>(x, Wc, logits, out);
}

// round 9
// speedup vs baseline: 1.8344x; 1.3416x over previous
#include <cuda_runtime.h>
#include <cuda_bf16.h>
#include <mma.h>
#include <cstdint>

using namespace nvcuda;

#define VOCAB   50257
#define M_TOK   4096
#define K_HID   1024
#define N_PAD   50304          // 393 * 128
#define NT      393
#define PARTW   400
#define NCLUST  3
#define NCHUNK  32             // K chunks of 32

// ---------------- scratch ----------------
__device__ __align__(128) __nv_bfloat16 g_xb[(size_t)M_TOK * K_HID];   // x bf16 [M][K]
__device__ __align__(128) __nv_bfloat16 g_lb[(size_t)K_HID * N_PAD];   // logits bf16 [K][N_PAD]
__device__ float g_part[(size_t)M_TOK * PARTW];
__device__ int   g_perm[M_TOK];
__device__ int   g_tokcl[M_TOK];
__device__ int   g_yint[M_TOK];
__device__ int   g_cfirst[M_TOK / 128];
__device__ int   g_clast[M_TOK / 128];

// ---------------- k_prep_x: x f32 -> bf16, vectorized (proven in R6) ----------------
__global__ void k_prep_x(const float4* __restrict__ x4) {
    int t = blockIdx.x * 256 + threadIdx.x;          // 8 halves per thread
    float4 a = x4[2 * t], b = x4[2 * t + 1];
    union { __nv_bfloat16 h[8]; uint4 u; } p;
    p.h[0] = __float2bfloat16(a.x); p.h[1] = __float2bfloat16(a.y);
    p.h[2] = __float2bfloat16(a.z); p.h[3] = __float2bfloat16(a.w);
    p.h[4] = __float2bfloat16(b.x); p.h[5] = __float2bfloat16(b.y);
    p.h[6] = __float2bfloat16(b.z); p.h[7] = __float2bfloat16(b.w);
    *(uint4*)(g_xb + (size_t)t * 8) = p.u;
}

// ---------------- k_prep_l: logits f32 [K][VOCAB] -> bf16 [K][N_PAD], 2 cols/thread ----------------
__global__ void k_prep_l(const float* __restrict__ logits) {
    int c2  = blockIdx.x * 128 + threadIdx.x;        // pair index, 0 .. 25151
    int k   = blockIdx.y;
    int col = c2 * 2;
    const float* row = logits + (size_t)k * VOCAB;
    float v0 = (col     < VOCAB) ? row[col]     : 0.0f;
    float v1 = (col + 1 < VOCAB) ? row[col + 1] : 0.0f;
    __nv_bfloat162 p;
    p.x = __float2bfloat16(v0);
    p.y = __float2bfloat16(v1);
    *(__nv_bfloat162*)(g_lb + (size_t)k * N_PAD + col) = p;
}

// ---------------- k_sort: decode y (int32/int64), group tokens by cluster ----------------
__global__ void k_sort(const int* __restrict__ y32) {
    __shared__ int cnt[NCLUST], cur[NCLUST];
    __shared__ int is64;
    int tid = threadIdx.x;
    if (tid == 0) {
        int odd = 0;
        for (int i = 0; i < 64; i++) odd |= y32[2 * i + 1];
        is64 = (odd == 0) ? 1 : 0;
    }
    if (tid < NCLUST) cnt[tid] = 0;
    __syncthreads();
    for (int t = tid; t < M_TOK; t += 1024) {
        int yi = is64 ? y32[2 * t] : y32[t];
        yi = max(0, min(VOCAB - 1, yi));
        g_yint[t] = yi;
        int c = yi < 20000 ? 0 : (yi < 40000 ? 1 : 2);
        g_tokcl[t] = c;
        atomicAdd(&cnt[c], 1);
    }
    __syncthreads();
    if (tid == 0) { cur[0] = 0; cur[1] = cnt[0]; cur[2] = cnt[0] + cnt[1]; }
    __syncthreads();
    for (int t = tid; t < M_TOK; t += 1024) {
        int pos = atomicAdd(&cur[g_tokcl[t]], 1);
        g_perm[pos] = t;
    }
    __syncthreads();
    if (tid < M_TOK / 128) {
        g_cfirst[tid] = g_tokcl[g_perm[tid * 128]];
        g_clast[tid]  = g_tokcl[g_perm[tid * 128 + 127]];
    }
}

// ---------------- k_gemm smem ----------------
#define A_PITCH 40     // halves per A row (80 B)
#define B_PITCH 136    // halves per B k-row (272 B)
#define P_PITCH 72     // floats per patch row
struct MLStage {
    __align__(16) __nv_bfloat16 A[128 * A_PITCH];   // 10240 B  [m][k] chunk K=32
    __align__(16) __nv_bfloat16 B[32 * B_PITCH];    //  8704 B  [k][n]
};
struct __align__(128) SmemU {
    union {
        MLStage st[2];                              // 37888 B mainloop
        struct {                                    // 19456 B epilogue
            float patch[4][16 * P_PITCH];
            float ep[128][2];
        } e;
    } u;
    int rowperm[128];
    int rowcl[128];
};

__device__ __forceinline__ void cp16(void* dst, const void* src) {
    uint32_t d = (uint32_t)__cvta_generic_to_shared(dst);
    asm volatile("cp.async.cg.shared.global [%0], [%1], 16;" :: "r"(d), "l"(src));
}

// ---------------- k_gemm: WMMA bf16, 4 warps, warp tile 64x64, cp.async double-buffered ----------------
__global__ __launch_bounds__(128, 2) void k_gemm() {
    const int m_tile = blockIdx.x, n_tile = blockIdx.y;
    const int TB[NCLUST] = {0, 156, 312};
    const int TE[NCLUST] = {157, 313, 393};
    {
        int cf = g_cfirst[m_tile], cl = g_clast[m_tile];
        if (n_tile < TB[cf] || n_tile >= TE[cl]) return;
    }

    __shared__ SmemU s;
    const int tid = threadIdx.x, lane = tid & 31, wid = tid >> 5;
    const int wm = wid >> 1, wn = wid & 1;           // 2(m) x 2(n) warps, 64x64 each

    {
        int o = g_perm[m_tile * 128 + tid];
        s.rowperm[tid] = o;
        s.rowcl[tid] = g_tokcl[o];
    }
    __syncthreads();

    wmma::fragment<wmma::accumulator, 16, 16, 16, float> acc[4][4];
#pragma unroll
    for (int fm = 0; fm < 4; fm++)
#pragma unroll
        for (int fn = 0; fn < 4; fn++) wmma::fill_fragment(acc[fm][fn], 0.0f);

    // stage c into buffer buf: A 128x4 16B-tasks, B 32x16 16B-tasks, 4+4 per thread
    auto issue = [&](int c, int buf) {
#pragma unroll
        for (int i = 0; i < 4; i++) {
            int t = tid + i * 128;                   // 0..511
            int ar = t >> 2, as = t & 3;
            cp16(&s.u.st[buf].A[ar * A_PITCH + as * 8],
                 g_xb + (size_t)s.rowperm[ar] * K_HID + c * 32 + as * 8);
            int br = t >> 4, bs = t & 15;
            cp16(&s.u.st[buf].B[br * B_PITCH + bs * 8],
                 g_lb + (size_t)(c * 32 + br) * N_PAD + (size_t)n_tile * 128 + bs * 8);
        }
        asm volatile("cp.async.commit_group;" ::: "memory");
    };

    issue(0, 0);
    for (int c = 0; c < NCHUNK; c++) {
        if (c + 1 < NCHUNK) {
            issue(c + 1, (c + 1) & 1);
            asm volatile("cp.async.wait_group 1;" ::: "memory");
        } else {
            asm volatile("cp.async.wait_group 0;" ::: "memory");
        }
        __syncthreads();

        const MLStage& st = s.u.st[c & 1];
#pragma unroll
        for (int ks = 0; ks < 2; ks++) {
            const int kk = ks * 16;
            wmma::fragment<wmma::matrix_b, 16, 16, 16, __nv_bfloat16, wmma::row_major> bf[4];
#pragma unroll
            for (int fn = 0; fn < 4; fn++)
                wmma::load_matrix_sync(bf[fn], &st.B[kk * B_PITCH + wn * 64 + fn * 16], B_PITCH);
#pragma unroll
            for (int fm = 0; fm < 4; fm++) {
                wmma::fragment<wmma::matrix_a, 16, 16, 16, __nv_bfloat16, wmma::row_major> af;
                wmma::load_matrix_sync(af, &st.A[(wm * 64 + fm * 16) * A_PITCH + kk], A_PITCH);
#pragma unroll
                for (int fn = 0; fn < 4; fn++)
                    wmma::mma_sync(acc[fm][fn], af, bf[fn], acc[fm][fn]);
            }
        }
        __syncthreads();
    }

    // Epilogue (reuses mainloop smem): exp + cluster-masked row sums, fixed order.
    const int r16 = lane & 15, cg = lane >> 4;       // lane -> (row, 32-col group)
    const int vbase = n_tile * 128 + wn * 64 + cg * 32;
#pragma unroll
    for (int fm = 0; fm < 4; fm++) {
        __syncwarp();
#pragma unroll
        for (int fn = 0; fn < 4; fn++)
            wmma::store_matrix_sync(&s.u.e.patch[wid][fn * 16], acc[fm][fn],
                                    P_PITCH, wmma::mem_row_major);
        __syncwarp();
        int rloc = wm * 64 + fm * 16 + r16;
        int crow = s.rowcl[rloc];
        float sum = 0.0f;
#pragma unroll
        for (int j = 0; j < 32; j++) {
            int vc = vbase + j;
            int ccol = vc < 20000 ? 0 : (vc < 40000 ? 1 : (vc < VOCAB ? 2 : 3));
            float v = s.u.e.patch[wid][r16 * P_PITCH + cg * 32 + j];
            if (ccol == crow) sum += __expf(v);
        }
        sum += __shfl_xor_sync(0xffffffffu, sum, 16);   // combine 32-col groups
        if (lane < 16) s.u.e.ep[rloc][wn] = sum;
        __syncwarp();
    }
    __syncthreads();
    {
        float tot = s.u.e.ep[tid][0] + s.u.e.ep[tid][1];   // fixed order
        g_part[(size_t)s.rowperm[tid] * PARTW + n_tile] = tot;
    }
}

// ---------------- k_final: per-token NLL (fp32), one warp per token ----------------
__global__ void k_final(const float* __restrict__ x,
                        const float* __restrict__ Wc, const float* __restrict__ logits,
                        float* __restrict__ out) {
    const int TB[NCLUST] = {0, 156, 312};
    const int TE[NCLUST] = {157, 313, 393};
    int warp = threadIdx.x >> 5, lane = threadIdx.x & 31;
    int token = blockIdx.x * 8 + warp;
    const float* xr = x + (size_t)token * K_HID;

    float xv[32];
#pragma unroll
    for (int i = 0; i < 32; i++) xv[i] = xr[i * 32 + lane];

    float s0 = 0.f, s1 = 0.f, s2 = 0.f;
#pragma unroll
    for (int i = 0; i < 32; i++) {
        int h = i * 32 + lane;
        s0 = fmaf(xv[i], Wc[h], s0);
        s1 = fmaf(xv[i], Wc[K_HID + h], s1);
        s2 = fmaf(xv[i], Wc[2 * K_HID + h], s2);
    }

    int yi = g_yint[token];
    int c  = g_tokcl[token];
    float tg = 0.f;
#pragma unroll
    for (int i = 0; i < 32; i++) {
        int h = i * 32 + lane;
        tg = fmaf(xv[i], logits[(size_t)h * VOCAB + yi], tg);
    }

    float se = 0.f;
    for (int t = TB[c] + lane; t < TE[c]; t += 32)
        se += g_part[(size_t)token * PARTW + t];

#pragma unroll
    for (int o = 16; o; o >>= 1) {
        s0 += __shfl_xor_sync(0xffffffffu, s0, o);
        s1 += __shfl_xor_sync(0xffffffffu, s1, o);
        s2 += __shfl_xor_sync(0xffffffffu, s2, o);
        tg += __shfl_xor_sync(0xffffffffu, tg, o);
        se += __shfl_xor_sync(0xffffffffu, se, o);
    }

    if (lane == 0) {
        float m = fmaxf(s0, fmaxf(s1, s2));
        float lse3 = m + logf(expf(s0 - m) + expf(s1 - m) + expf(s2 - m));
        float sc = (c == 0) ? s0 : ((c == 1) ? s1 : s2);
        out[token] = -(sc - lse3) - (tg - logf(se));
    }
}

// ---------------- launch ----------------
extern "C" void kernel_launch(void* const* d_in, const int* in_sizes, int n_in,
                              void* d_out, int out_size) {
    const float* x      = (const float*)d_in[0];
    const int*   y32    = (const int*)d_in[1];
    const float* Wc     = (const float*)d_in[2];
    const float* logits = (const float*)d_in[3];
    float*       out    = (float*)d_out;

    k_prep_x<<<M_TOK * K_HID / (256 * 8), 256>>>((const float4*)x);
    k_prep_l<<<dim3(N_PAD / 256, K_HID), 128>>>(logits);
    k_sort<<<1, 1024>>>(y32);
    k_gemm<<<dim3(M_TOK / 128, NT), 128>>>();     // m fastest -> B stripe L2-resident
    k_final<<<M_TOK / 8, 256>>>(x, Wc, logits, out);
}